// round 1
// baseline (speedup 1.0000x reference)
#include <cuda_runtime.h>
#include <cuda_bf16.h>
#include <math.h>

// Problem constants
#define B_  2
#define S_  2048
#define H_  1024
#define NH_ 16
#define HD_ 64
#define M_  (B_ * S_)          // 4096 rows
#define LN_EPS 1e-5f

// ---------------------------------------------------------------------------
// Scratch (allocation-free: __device__ globals)
// ---------------------------------------------------------------------------
__device__ float g_Q[M_ * H_];
__device__ float g_K[M_ * H_];
__device__ float g_V[M_ * H_];
__device__ float g_C[M_ * H_];   // attention context; later x = attn_out+resid reuses g_Q

// ---------------------------------------------------------------------------
// GEMM (NT): C[m][n] = sum_k A[m][k] * W[n][k] + bias[n] (+ resid[m][n])
// A: [M,K] row-major, W: [N,K] row-major.
// Tiles: 64x64, K-tile 16. 256 threads, each computes 4x4.
// ---------------------------------------------------------------------------
#define TM 64
#define TN 64
#define TK 16
#define SPAD 68   // smem row stride (floats), 16B-aligned, conflict-light

__global__ __launch_bounds__(256)
void gemm_nt(const float* __restrict__ A, const float* __restrict__ W,
             const float* __restrict__ bias, const float* __restrict__ resid,
             float* __restrict__ C, int M, int N, int K)
{
    __shared__ float As[TK][SPAD];   // As[kk][m]
    __shared__ float Bs[TK][SPAD];   // Bs[kk][n]

    const int tid = threadIdx.x;
    const int tx = tid & 15;          // 0..15 -> n groups
    const int ty = tid >> 4;          // 0..15 -> m groups
    const int row0 = blockIdx.y * TM;
    const int col0 = blockIdx.x * TN;

    // load mapping: one float4 per thread per tile
    const int lrow = tid >> 2;        // 0..63
    const int lc4  = tid & 3;         // 0..3  (k-offset /4)

    float acc[4][4];
    #pragma unroll
    for (int i = 0; i < 4; i++)
        #pragma unroll
        for (int j = 0; j < 4; j++) acc[i][j] = 0.f;

    for (int k0 = 0; k0 < K; k0 += TK) {
        float4 av = *(const float4*)&A[(size_t)(row0 + lrow) * K + k0 + lc4 * 4];
        float4 bv = *(const float4*)&W[(size_t)(col0 + lrow) * K + k0 + lc4 * 4];
        As[lc4 * 4 + 0][lrow] = av.x;
        As[lc4 * 4 + 1][lrow] = av.y;
        As[lc4 * 4 + 2][lrow] = av.z;
        As[lc4 * 4 + 3][lrow] = av.w;
        Bs[lc4 * 4 + 0][lrow] = bv.x;
        Bs[lc4 * 4 + 1][lrow] = bv.y;
        Bs[lc4 * 4 + 2][lrow] = bv.z;
        Bs[lc4 * 4 + 3][lrow] = bv.w;
        __syncthreads();

        #pragma unroll
        for (int kk = 0; kk < TK; kk++) {
            float a[4], b[4];
            #pragma unroll
            for (int i = 0; i < 4; i++) a[i] = As[kk][ty * 4 + i];
            #pragma unroll
            for (int j = 0; j < 4; j++) b[j] = Bs[kk][tx * 4 + j];
            #pragma unroll
            for (int i = 0; i < 4; i++)
                #pragma unroll
                for (int j = 0; j < 4; j++)
                    acc[i][j] = fmaf(a[i], b[j], acc[i][j]);
        }
        __syncthreads();
    }

    #pragma unroll
    for (int i = 0; i < 4; i++) {
        int m = row0 + ty * 4 + i;
        #pragma unroll
        for (int j = 0; j < 4; j++) {
            int n = col0 + tx * 4 + j;
            float v = acc[i][j] + bias[n];
            if (resid) v += resid[(size_t)m * N + n];
            C[(size_t)m * N + n] = v;
        }
    }
}

// ---------------------------------------------------------------------------
// Flash attention: per (qblock, head, batch). 128 threads, 1 q-row per thread.
// K/V tiles of 64 rows in smem. Online softmax with 16-wide score chunks.
// Q/K/V layout: [B,S,H] with head h occupying columns [h*64, h*64+64).
// ---------------------------------------------------------------------------
#define BQ  128
#define BKV 64

__global__ __launch_bounds__(128)
void flash_attn(const float* __restrict__ Q, const float* __restrict__ K,
                const float* __restrict__ V, float* __restrict__ O)
{
    __shared__ float Ks[BKV][HD_];
    __shared__ float Vs[BKV][HD_];

    const int tid = threadIdx.x;
    const int b = blockIdx.z;
    const int h = blockIdx.y;
    const int qrow = blockIdx.x * BQ + tid;

    const float scale = 0.125f;   // 1/sqrt(64)

    const float* qp = Q + ((size_t)(b * S_ + qrow)) * H_ + h * HD_;
    float q[HD_];
    #pragma unroll
    for (int d4 = 0; d4 < 16; d4++) {
        float4 t = *(const float4*)&qp[d4 * 4];
        q[d4 * 4 + 0] = t.x; q[d4 * 4 + 1] = t.y;
        q[d4 * 4 + 2] = t.z; q[d4 * 4 + 3] = t.w;
    }

    float accv[HD_];
    #pragma unroll
    for (int d = 0; d < HD_; d++) accv[d] = 0.f;
    float m = -1e30f, l = 0.f;

    for (int kv0 = 0; kv0 < S_; kv0 += BKV) {
        // load K/V tiles (1024 float4 each, 128 threads -> 8 each)
        #pragma unroll
        for (int i = 0; i < 8; i++) {
            int idx = tid + i * 128;          // float4 index 0..1023
            int r = idx >> 4, c4 = idx & 15;
            size_t g = ((size_t)(b * S_ + kv0 + r)) * H_ + h * HD_ + c4 * 4;
            *(float4*)&Ks[r][c4 * 4] = *(const float4*)&K[g];
            *(float4*)&Vs[r][c4 * 4] = *(const float4*)&V[g];
        }
        __syncthreads();

        #pragma unroll
        for (int c0 = 0; c0 < BKV; c0 += 16) {
            float sc[16];
            float mt = m;
            #pragma unroll
            for (int j = 0; j < 16; j++) {
                const float4* kp = (const float4*)&Ks[c0 + j][0];
                float s = 0.f;
                #pragma unroll
                for (int d4 = 0; d4 < 16; d4++) {
                    float4 kk = kp[d4];
                    s = fmaf(q[4 * d4 + 0], kk.x, s);
                    s = fmaf(q[4 * d4 + 1], kk.y, s);
                    s = fmaf(q[4 * d4 + 2], kk.z, s);
                    s = fmaf(q[4 * d4 + 3], kk.w, s);
                }
                s *= scale;
                sc[j] = s;
                mt = fmaxf(mt, s);
            }
            if (mt > m) {
                float corr = __expf(m - mt);
                l *= corr;
                #pragma unroll
                for (int d = 0; d < HD_; d++) accv[d] *= corr;
                m = mt;
            }
            #pragma unroll
            for (int j = 0; j < 16; j++) {
                float p = __expf(sc[j] - m);
                l += p;
                const float4* vp = (const float4*)&Vs[c0 + j][0];
                #pragma unroll
                for (int d4 = 0; d4 < 16; d4++) {
                    float4 vv = vp[d4];
                    accv[4 * d4 + 0] = fmaf(p, vv.x, accv[4 * d4 + 0]);
                    accv[4 * d4 + 1] = fmaf(p, vv.y, accv[4 * d4 + 1]);
                    accv[4 * d4 + 2] = fmaf(p, vv.z, accv[4 * d4 + 2]);
                    accv[4 * d4 + 3] = fmaf(p, vv.w, accv[4 * d4 + 3]);
                }
            }
        }
        __syncthreads();
    }

    const float inv = 1.f / l;
    float* op = O + ((size_t)(b * S_ + qrow)) * H_ + h * HD_;
    #pragma unroll
    for (int d4 = 0; d4 < 16; d4++) {
        float4 t;
        t.x = accv[4 * d4 + 0] * inv;
        t.y = accv[4 * d4 + 1] * inv;
        t.z = accv[4 * d4 + 2] * inv;
        t.w = accv[4 * d4 + 3] * inv;
        *(float4*)&op[d4 * 4] = t;
    }
}

// ---------------------------------------------------------------------------
// LayerNorm over H=1024 per row. One block (256 threads) per row.
// ---------------------------------------------------------------------------
__global__ __launch_bounds__(256)
void layernorm(const float* __restrict__ X, const float* __restrict__ gamma,
               const float* __restrict__ beta, float* __restrict__ Out)
{
    __shared__ float red[8];
    __shared__ float bc;

    const int row = blockIdx.x;
    const int tid = threadIdx.x;
    const float* x = X + (size_t)row * H_;

    float v[4];
    float s = 0.f;
    #pragma unroll
    for (int i = 0; i < 4; i++) { v[i] = x[tid + 256 * i]; s += v[i]; }

    #pragma unroll
    for (int o = 16; o > 0; o >>= 1) s += __shfl_xor_sync(0xffffffffu, s, o);
    if ((tid & 31) == 0) red[tid >> 5] = s;
    __syncthreads();
    if (tid == 0) {
        float t = 0.f;
        #pragma unroll
        for (int i = 0; i < 8; i++) t += red[i];
        bc = t * (1.f / H_);
    }
    __syncthreads();
    const float mu = bc;

    float vs = 0.f;
    #pragma unroll
    for (int i = 0; i < 4; i++) { float d = v[i] - mu; vs += d * d; }
    #pragma unroll
    for (int o = 16; o > 0; o >>= 1) vs += __shfl_xor_sync(0xffffffffu, vs, o);
    __syncthreads();                 // protect red[] reuse
    if ((tid & 31) == 0) red[tid >> 5] = vs;
    __syncthreads();
    if (tid == 0) {
        float t = 0.f;
        #pragma unroll
        for (int i = 0; i < 8; i++) t += red[i];
        bc = t * (1.f / H_);
    }
    __syncthreads();
    const float rstd = rsqrtf(bc + LN_EPS);

    #pragma unroll
    for (int i = 0; i < 4; i++) {
        int col = tid + 256 * i;
        Out[(size_t)row * H_ + col] = (v[i] - mu) * rstd * gamma[col] + beta[col];
    }
}

// ---------------------------------------------------------------------------
// Launch
// ---------------------------------------------------------------------------
extern "C" void kernel_launch(void* const* d_in, const int* in_sizes, int n_in,
                              void* d_out, int out_size)
{
    const float* hs    = (const float*)d_in[0];
    const float* Wq    = (const float*)d_in[1];
    const float* bq    = (const float*)d_in[2];
    const float* Wk    = (const float*)d_in[3];
    const float* bk    = (const float*)d_in[4];
    const float* Wv    = (const float*)d_in[5];
    const float* bv    = (const float*)d_in[6];
    const float* Wd    = (const float*)d_in[7];
    const float* bd    = (const float*)d_in[8];
    const float* gamma = (const float*)d_in[9];
    const float* beta  = (const float*)d_in[10];
    float* out = (float*)d_out;

    float *Qp, *Kp, *Vp, *Cp;
    cudaGetSymbolAddress((void**)&Qp, g_Q);
    cudaGetSymbolAddress((void**)&Kp, g_K);
    cudaGetSymbolAddress((void**)&Vp, g_V);
    cudaGetSymbolAddress((void**)&Cp, g_C);

    dim3 gg(H_ / TN, M_ / TM);   // (16, 64)

    gemm_nt<<<gg, 256>>>(hs, Wq, bq, nullptr, Qp, M_, H_, H_);
    gemm_nt<<<gg, 256>>>(hs, Wk, bk, nullptr, Kp, M_, H_, H_);
    gemm_nt<<<gg, 256>>>(hs, Wv, bv, nullptr, Vp, M_, H_, H_);

    flash_attn<<<dim3(S_ / BQ, NH_, B_), 128>>>(Qp, Kp, Vp, Cp);

    // x = ctx @ Wd^T + bd + hidden  -> reuse g_Q as x buffer
    gemm_nt<<<gg, 256>>>(Cp, Wd, bd, hs, Qp, M_, H_, H_);

    layernorm<<<M_, 256>>>(Qp, gamma, beta, out);
}

// round 3
// speedup vs baseline: 1.1945x; 1.1945x over previous
#include <cuda_runtime.h>
#include <cuda_bf16.h>
#include <math.h>
#include <stdint.h>

// Problem constants
#define B_  2
#define S_  2048
#define H_  1024
#define NH_ 16
#define HD_ 64
#define M_  (B_ * S_)          // 4096 rows
#define LN_EPS 1e-5f

// ---------------------------------------------------------------------------
// Helpers
// ---------------------------------------------------------------------------
__device__ __forceinline__ uint32_t smem_to_u32(const void* p) {
    uint32_t a;
    asm("{ .reg .u64 t; cvta.to.shared.u64 t, %1; cvt.u32.u64 %0, t; }" : "=r"(a) : "l"(p));
    return a;
}

#define CP_ASYNC16(dst, src) \
    asm volatile("cp.async.cg.shared.global [%0], [%1], 16;" :: "r"(dst), "l"(src))
#define CP_COMMIT() asm volatile("cp.async.commit_group;" ::: "memory")
#define CP_WAIT0()  asm volatile("cp.async.wait_group 0;" ::: "memory")

__device__ __forceinline__ void ldsm_x4(uint32_t& r0, uint32_t& r1, uint32_t& r2, uint32_t& r3,
                                        uint32_t addr) {
    asm volatile("ldmatrix.sync.aligned.m8n8.x4.shared.b16 {%0,%1,%2,%3}, [%4];"
                 : "=r"(r0), "=r"(r1), "=r"(r2), "=r"(r3) : "r"(addr));
}
__device__ __forceinline__ void ldsm_x2(uint32_t& r0, uint32_t& r1, uint32_t addr) {
    asm volatile("ldmatrix.sync.aligned.m8n8.x2.shared.b16 {%0,%1}, [%2];"
                 : "=r"(r0), "=r"(r1) : "r"(addr));
}
__device__ __forceinline__ void mma_16816(float* c, uint32_t a0, uint32_t a1, uint32_t a2,
                                          uint32_t a3, uint32_t b0, uint32_t b1) {
    asm volatile("mma.sync.aligned.m16n8k16.row.col.f32.bf16.bf16.f32 "
                 "{%0,%1,%2,%3}, {%4,%5,%6,%7}, {%8,%9}, {%0,%1,%2,%3};"
                 : "+f"(c[0]), "+f"(c[1]), "+f"(c[2]), "+f"(c[3])
                 : "r"(a0), "r"(a1), "r"(a2), "r"(a3), "r"(b0), "r"(b1));
}

// ---------------------------------------------------------------------------
// Scratch (allocation-free: __device__ globals)
// ---------------------------------------------------------------------------
__device__ float g_Q[M_ * H_];
__device__ float g_K[M_ * H_];
__device__ float g_V[M_ * H_];
__device__ float g_C[M_ * H_];
__device__ __nv_bfloat16 g_hsh[M_ * H_];
__device__ __nv_bfloat16 g_hsl[M_ * H_];
__device__ __nv_bfloat16 g_Ch[M_ * H_];
__device__ __nv_bfloat16 g_Cl[M_ * H_];
__device__ __nv_bfloat16 g_Wh[4 * H_ * H_];
__device__ __nv_bfloat16 g_Wl[4 * H_ * H_];

// ---------------------------------------------------------------------------
// fp32 -> (bf16 hi, bf16 lo) split, vectorized
// ---------------------------------------------------------------------------
__global__ __launch_bounds__(256)
void split_kernel(const float* __restrict__ x, __nv_bfloat16* __restrict__ hi,
                  __nv_bfloat16* __restrict__ lo, int n)
{
    int i = (blockIdx.x * 256 + threadIdx.x) * 4;
    if (i >= n) return;
    float4 v = *(const float4*)(x + i);
    __nv_bfloat16 h0 = __float2bfloat16(v.x);
    __nv_bfloat16 h1 = __float2bfloat16(v.y);
    __nv_bfloat16 h2 = __float2bfloat16(v.z);
    __nv_bfloat16 h3 = __float2bfloat16(v.w);
    __nv_bfloat16 l0 = __float2bfloat16(v.x - __bfloat162float(h0));
    __nv_bfloat16 l1 = __float2bfloat16(v.y - __bfloat162float(h1));
    __nv_bfloat16 l2 = __float2bfloat16(v.z - __bfloat162float(h2));
    __nv_bfloat16 l3 = __float2bfloat16(v.w - __bfloat162float(h3));
    __nv_bfloat162* hp = (__nv_bfloat162*)(hi + i);
    __nv_bfloat162* lp = (__nv_bfloat162*)(lo + i);
    hp[0] = __nv_bfloat162(h0, h1);
    hp[1] = __nv_bfloat162(h2, h3);
    lp[0] = __nv_bfloat162(l0, l1);
    lp[1] = __nv_bfloat162(l2, l3);
}

// ---------------------------------------------------------------------------
// mma.sync GEMM: C[m][n] = sum_k A[m][k]*W[n][k] + bias[n] (+resid)
// 3-term bf16 split over concatenated K. CTA 128x128, BK=32, 8 warps (2x4),
// warp tile 64x32. Double-buffered cp.async. Padded smem stride 40 bf16.
// ---------------------------------------------------------------------------
#define SPAD_G 40          // smem row stride in bf16 (80 B, conflict-free ldmatrix)
#define GK_ITERS 96        // 3 segments * (1024/32)

__global__ __launch_bounds__(256)
void gemm_mma(const __nv_bfloat16* __restrict__ Ah, const __nv_bfloat16* __restrict__ Al,
              const __nv_bfloat16* __restrict__ Wh, const __nv_bfloat16* __restrict__ Wl,
              const float* __restrict__ bias, const float* __restrict__ resid,
              float* __restrict__ C)
{
    __shared__ __nv_bfloat16 As[2][128][SPAD_G];
    __shared__ __nv_bfloat16 Bs[2][128][SPAD_G];

    const int tid = threadIdx.x;
    const int wid = tid >> 5;
    const int lane = tid & 31;
    const int wm = wid & 1;          // 0..1 -> m halves of 64
    const int wn = wid >> 1;         // 0..3 -> n quarters of 32
    const int row0 = blockIdx.y * 128;
    const int col0 = blockIdx.x * 128;

    const __nv_bfloat16* aSeg[3] = {Ah, Ah, Al};
    const __nv_bfloat16* wSeg[3] = {Wh, Wl, Wh};

    // loader: per stage 512 A-chunks + 512 B-chunks of 16B; 256 threads -> 2+2 each
    const int l_row = tid >> 1;                 // 0..127
    const int l_c8a = (tid & 1) * 2;            // 0 or 2 (two chunks each: c8, c8+1)

    auto load_stage = [&](int it, int st) {
        const int seg = it >> 5;
        const int k0 = (it & 31) * 32;
        const __nv_bfloat16* Ag = aSeg[seg];
        const __nv_bfloat16* Wg = wSeg[seg];
        uint32_t sa = smem_to_u32(&As[st][l_row][0]);
        uint32_t sb = smem_to_u32(&Bs[st][l_row][0]);
        const __nv_bfloat16* ga = Ag + (size_t)(row0 + l_row) * H_ + k0;
        const __nv_bfloat16* gb = Wg + (size_t)(col0 + l_row) * H_ + k0;
        #pragma unroll
        for (int c = 0; c < 2; c++) {
            int c8 = l_c8a + c;                 // 0..3
            CP_ASYNC16(sa + c8 * 16, ga + c8 * 8);
            CP_ASYNC16(sb + c8 * 16, gb + c8 * 8);
        }
    };

    float acc[4][4][4];
    #pragma unroll
    for (int i = 0; i < 4; i++)
        #pragma unroll
        for (int j = 0; j < 4; j++)
            #pragma unroll
            for (int e = 0; e < 4; e++) acc[i][j][e] = 0.f;

    load_stage(0, 0);
    CP_COMMIT();

    for (int it = 0; it < GK_ITERS; it++) {
        CP_WAIT0();
        __syncthreads();
        if (it + 1 < GK_ITERS) load_stage(it + 1, (it + 1) & 1);
        CP_COMMIT();

        const int st = it & 1;
        // fragment base addresses
        const int t16 = lane & 15;
        uint32_t aBase = smem_to_u32(&As[st][wm * 64 + t16][0]);
        uint32_t bBase = smem_to_u32(&Bs[st][wn * 32 + (t16 & 7)][0]);
        const int aKoff = (lane >> 4) * 8;       // 0 or 8
        const int bKoff = (t16 >> 3) * 8;        // 0 or 8

        #pragma unroll
        for (int ks = 0; ks < 2; ks++) {
            const int k = ks * 16;
            uint32_t a[4][4];
            #pragma unroll
            for (int mf = 0; mf < 4; mf++)
                ldsm_x4(a[mf][0], a[mf][1], a[mf][2], a[mf][3],
                        aBase + (mf * 16 * SPAD_G + k + aKoff) * 2);
            uint32_t b[4][2];
            #pragma unroll
            for (int nf = 0; nf < 4; nf++)
                ldsm_x2(b[nf][0], b[nf][1],
                        bBase + (nf * 8 * SPAD_G + k + bKoff) * 2);
            #pragma unroll
            for (int mf = 0; mf < 4; mf++)
                #pragma unroll
                for (int nf = 0; nf < 4; nf++)
                    mma_16816(acc[mf][nf], a[mf][0], a[mf][1], a[mf][2], a[mf][3],
                              b[nf][0], b[nf][1]);
        }
        __syncthreads();
    }

    // Epilogue
    const int mBase = row0 + wm * 64 + (lane >> 2);
    const int nBase = col0 + wn * 32 + (lane & 3) * 2;
    #pragma unroll
    for (int mf = 0; mf < 4; mf++) {
        #pragma unroll
        for (int nf = 0; nf < 4; nf++) {
            const int m0 = mBase + mf * 16;
            const int n0 = nBase + nf * 8;
            float bx = bias[n0], by = bias[n0 + 1];
            float2 v0 = make_float2(acc[mf][nf][0] + bx, acc[mf][nf][1] + by);
            float2 v1 = make_float2(acc[mf][nf][2] + bx, acc[mf][nf][3] + by);
            if (resid) {
                float2 r0 = *(const float2*)&resid[(size_t)m0 * H_ + n0];
                float2 r1 = *(const float2*)&resid[(size_t)(m0 + 8) * H_ + n0];
                v0.x += r0.x; v0.y += r0.y;
                v1.x += r1.x; v1.y += r1.y;
            }
            *(float2*)&C[(size_t)m0 * H_ + n0] = v0;
            *(float2*)&C[(size_t)(m0 + 8) * H_ + n0] = v1;
        }
    }
}

// ---------------------------------------------------------------------------
// Flash attention (fp32, unchanged)
// ---------------------------------------------------------------------------
#define BQ  128
#define BKV 64

__global__ __launch_bounds__(128)
void flash_attn(const float* __restrict__ Q, const float* __restrict__ K,
                const float* __restrict__ V, float* __restrict__ O)
{
    __shared__ float Ks[BKV][HD_];
    __shared__ float Vs[BKV][HD_];

    const int tid = threadIdx.x;
    const int b = blockIdx.z;
    const int h = blockIdx.y;
    const int qrow = blockIdx.x * BQ + tid;

    const float scale = 0.125f;

    const float* qp = Q + ((size_t)(b * S_ + qrow)) * H_ + h * HD_;
    float q[HD_];
    #pragma unroll
    for (int d4 = 0; d4 < 16; d4++) {
        float4 t = *(const float4*)&qp[d4 * 4];
        q[d4 * 4 + 0] = t.x; q[d4 * 4 + 1] = t.y;
        q[d4 * 4 + 2] = t.z; q[d4 * 4 + 3] = t.w;
    }

    float accv[HD_];
    #pragma unroll
    for (int d = 0; d < HD_; d++) accv[d] = 0.f;
    float m = -1e30f, l = 0.f;

    for (int kv0 = 0; kv0 < S_; kv0 += BKV) {
        #pragma unroll
        for (int i = 0; i < 8; i++) {
            int idx = tid + i * 128;
            int r = idx >> 4, c4 = idx & 15;
            size_t g = ((size_t)(b * S_ + kv0 + r)) * H_ + h * HD_ + c4 * 4;
            *(float4*)&Ks[r][c4 * 4] = *(const float4*)&K[g];
            *(float4*)&Vs[r][c4 * 4] = *(const float4*)&V[g];
        }
        __syncthreads();

        #pragma unroll
        for (int c0 = 0; c0 < BKV; c0 += 16) {
            float sc[16];
            float mt = m;
            #pragma unroll
            for (int j = 0; j < 16; j++) {
                const float4* kp = (const float4*)&Ks[c0 + j][0];
                float s = 0.f;
                #pragma unroll
                for (int d4 = 0; d4 < 16; d4++) {
                    float4 kk = kp[d4];
                    s = fmaf(q[4 * d4 + 0], kk.x, s);
                    s = fmaf(q[4 * d4 + 1], kk.y, s);
                    s = fmaf(q[4 * d4 + 2], kk.z, s);
                    s = fmaf(q[4 * d4 + 3], kk.w, s);
                }
                s *= scale;
                sc[j] = s;
                mt = fmaxf(mt, s);
            }
            if (mt > m) {
                float corr = __expf(m - mt);
                l *= corr;
                #pragma unroll
                for (int d = 0; d < HD_; d++) accv[d] *= corr;
                m = mt;
            }
            #pragma unroll
            for (int j = 0; j < 16; j++) {
                float p = __expf(sc[j] - m);
                l += p;
                const float4* vp = (const float4*)&Vs[c0 + j][0];
                #pragma unroll
                for (int d4 = 0; d4 < 16; d4++) {
                    float4 vv = vp[d4];
                    accv[4 * d4 + 0] = fmaf(p, vv.x, accv[4 * d4 + 0]);
                    accv[4 * d4 + 1] = fmaf(p, vv.y, accv[4 * d4 + 1]);
                    accv[4 * d4 + 2] = fmaf(p, vv.z, accv[4 * d4 + 2]);
                    accv[4 * d4 + 3] = fmaf(p, vv.w, accv[4 * d4 + 3]);
                }
            }
        }
        __syncthreads();
    }

    const float inv = 1.f / l;
    float* op = O + ((size_t)(b * S_ + qrow)) * H_ + h * HD_;
    #pragma unroll
    for (int d4 = 0; d4 < 16; d4++) {
        float4 t;
        t.x = accv[4 * d4 + 0] * inv;
        t.y = accv[4 * d4 + 1] * inv;
        t.z = accv[4 * d4 + 2] * inv;
        t.w = accv[4 * d4 + 3] * inv;
        *(float4*)&op[d4 * 4] = t;
    }
}

// ---------------------------------------------------------------------------
// LayerNorm (unchanged)
// ---------------------------------------------------------------------------
__global__ __launch_bounds__(256)
void layernorm(const float* __restrict__ X, const float* __restrict__ gamma,
               const float* __restrict__ beta, float* __restrict__ Out)
{
    __shared__ float red[8];
    __shared__ float bc;

    const int row = blockIdx.x;
    const int tid = threadIdx.x;
    const float* x = X + (size_t)row * H_;

    float v[4];
    float s = 0.f;
    #pragma unroll
    for (int i = 0; i < 4; i++) { v[i] = x[tid + 256 * i]; s += v[i]; }

    #pragma unroll
    for (int o = 16; o > 0; o >>= 1) s += __shfl_xor_sync(0xffffffffu, s, o);
    if ((tid & 31) == 0) red[tid >> 5] = s;
    __syncthreads();
    if (tid == 0) {
        float t = 0.f;
        #pragma unroll
        for (int i = 0; i < 8; i++) t += red[i];
        bc = t * (1.f / H_);
    }
    __syncthreads();
    const float mu = bc;

    float vs = 0.f;
    #pragma unroll
    for (int i = 0; i < 4; i++) { float d = v[i] - mu; vs += d * d; }
    #pragma unroll
    for (int o = 16; o > 0; o >>= 1) vs += __shfl_xor_sync(0xffffffffu, vs, o);
    __syncthreads();
    if ((tid & 31) == 0) red[tid >> 5] = vs;
    __syncthreads();
    if (tid == 0) {
        float t = 0.f;
        #pragma unroll
        for (int i = 0; i < 8; i++) t += red[i];
        bc = t * (1.f / H_);
    }
    __syncthreads();
    const float rstd = rsqrtf(bc + LN_EPS);

    #pragma unroll
    for (int i = 0; i < 4; i++) {
        int col = tid + 256 * i;
        Out[(size_t)row * H_ + col] = (v[i] - mu) * rstd * gamma[col] + beta[col];
    }
}

// ---------------------------------------------------------------------------
// Launch
// ---------------------------------------------------------------------------
extern "C" void kernel_launch(void* const* d_in, const int* in_sizes, int n_in,
                              void* d_out, int out_size)
{
    const float* hs    = (const float*)d_in[0];
    const float* Wq    = (const float*)d_in[1];
    const float* bq    = (const float*)d_in[2];
    const float* Wk    = (const float*)d_in[3];
    const float* bk    = (const float*)d_in[4];
    const float* Wv    = (const float*)d_in[5];
    const float* bv    = (const float*)d_in[6];
    const float* Wd    = (const float*)d_in[7];
    const float* bd    = (const float*)d_in[8];
    const float* gamma = (const float*)d_in[9];
    const float* beta  = (const float*)d_in[10];
    float* out = (float*)d_out;

    float *Qp, *Kp, *Vp, *Cp;
    __nv_bfloat16 *hsh, *hsl, *Ch, *Cl, *Whp, *Wlp;
    cudaGetSymbolAddress((void**)&Qp, g_Q);
    cudaGetSymbolAddress((void**)&Kp, g_K);
    cudaGetSymbolAddress((void**)&Vp, g_V);
    cudaGetSymbolAddress((void**)&Cp, g_C);
    cudaGetSymbolAddress((void**)&hsh, g_hsh);
    cudaGetSymbolAddress((void**)&hsl, g_hsl);
    cudaGetSymbolAddress((void**)&Ch, g_Ch);
    cudaGetSymbolAddress((void**)&Cl, g_Cl);
    cudaGetSymbolAddress((void**)&Whp, g_Wh);
    cudaGetSymbolAddress((void**)&Wlp, g_Wl);

    const int nAct = M_ * H_;   // 4M elems
    const int nW   = H_ * H_;   // 1M elems

    // splits
    split_kernel<<<nAct / (256 * 4), 256>>>(hs, hsh, hsl, nAct);
    split_kernel<<<nW / (256 * 4), 256>>>(Wq, Whp + 0 * nW, Wlp + 0 * nW, nW);
    split_kernel<<<nW / (256 * 4), 256>>>(Wk, Whp + 1 * nW, Wlp + 1 * nW, nW);
    split_kernel<<<nW / (256 * 4), 256>>>(Wv, Whp + 2 * nW, Wlp + 2 * nW, nW);
    split_kernel<<<nW / (256 * 4), 256>>>(Wd, Whp + 3 * nW, Wlp + 3 * nW, nW);

    dim3 gg(H_ / 128, M_ / 128);   // (8, 32)
    gemm_mma<<<gg, 256>>>(hsh, hsl, Whp + 0 * nW, Wlp + 0 * nW, bq, nullptr, Qp);
    gemm_mma<<<gg, 256>>>(hsh, hsl, Whp + 1 * nW, Wlp + 1 * nW, bk, nullptr, Kp);
    gemm_mma<<<gg, 256>>>(hsh, hsl, Whp + 2 * nW, Wlp + 2 * nW, bv, nullptr, Vp);

    flash_attn<<<dim3(S_ / BQ, NH_, B_), 128>>>(Qp, Kp, Vp, Cp);

    split_kernel<<<nAct / (256 * 4), 256>>>(Cp, Ch, Cl, nAct);
    gemm_mma<<<gg, 256>>>(Ch, Cl, Whp + 3 * nW, Wlp + 3 * nW, bd, hs, Qp);

    layernorm<<<M_, 256>>>(Qp, gamma, beta, out);
}

// round 4
// speedup vs baseline: 3.8292x; 3.2056x over previous
#include <cuda_runtime.h>
#include <cuda_bf16.h>
#include <math.h>
#include <stdint.h>

// Problem constants
#define B_  2
#define S_  2048
#define H_  1024
#define NH_ 16
#define HD_ 64
#define M_  (B_ * S_)          // 4096 rows
#define LN_EPS 1e-5f

// ---------------------------------------------------------------------------
// Helpers
// ---------------------------------------------------------------------------
__device__ __forceinline__ uint32_t smem_to_u32(const void* p) {
    uint32_t a;
    asm("{ .reg .u64 t; cvta.to.shared.u64 t, %1; cvt.u32.u64 %0, t; }" : "=r"(a) : "l"(p));
    return a;
}

#define CP_ASYNC16(dst, src) \
    asm volatile("cp.async.cg.shared.global [%0], [%1], 16;" :: "r"(dst), "l"(src))
#define CP_COMMIT() asm volatile("cp.async.commit_group;" ::: "memory")
#define CP_WAIT0()  asm volatile("cp.async.wait_group 0;" ::: "memory")

__device__ __forceinline__ void ldsm_x4(uint32_t& r0, uint32_t& r1, uint32_t& r2, uint32_t& r3,
                                        uint32_t addr) {
    asm volatile("ldmatrix.sync.aligned.m8n8.x4.shared.b16 {%0,%1,%2,%3}, [%4];"
                 : "=r"(r0), "=r"(r1), "=r"(r2), "=r"(r3) : "r"(addr));
}
__device__ __forceinline__ void ldsm_x2(uint32_t& r0, uint32_t& r1, uint32_t addr) {
    asm volatile("ldmatrix.sync.aligned.m8n8.x2.shared.b16 {%0,%1}, [%2];"
                 : "=r"(r0), "=r"(r1) : "r"(addr));
}
__device__ __forceinline__ void ldsm_x4t(uint32_t& r0, uint32_t& r1, uint32_t& r2, uint32_t& r3,
                                         uint32_t addr) {
    asm volatile("ldmatrix.sync.aligned.m8n8.x4.trans.shared.b16 {%0,%1,%2,%3}, [%4];"
                 : "=r"(r0), "=r"(r1), "=r"(r2), "=r"(r3) : "r"(addr));
}
__device__ __forceinline__ void mma_16816(float* c, uint32_t a0, uint32_t a1, uint32_t a2,
                                          uint32_t a3, uint32_t b0, uint32_t b1) {
    asm volatile("mma.sync.aligned.m16n8k16.row.col.f32.bf16.bf16.f32 "
                 "{%0,%1,%2,%3}, {%4,%5,%6,%7}, {%8,%9}, {%0,%1,%2,%3};"
                 : "+f"(c[0]), "+f"(c[1]), "+f"(c[2]), "+f"(c[3])
                 : "r"(a0), "r"(a1), "r"(a2), "r"(a3), "r"(b0), "r"(b1));
}

__device__ __forceinline__ uint32_t pack_bf2(float x, float y) {
    __nv_bfloat162 t = __floats2bfloat162_rn(x, y);
    return *(uint32_t*)&t;
}

// ---------------------------------------------------------------------------
// Scratch (allocation-free: __device__ globals)
// ---------------------------------------------------------------------------
__device__ float g_X[M_ * H_];                 // dense out + residual
__device__ __nv_bfloat16 g_Qh[M_ * H_];
__device__ __nv_bfloat16 g_Ql[M_ * H_];
__device__ __nv_bfloat16 g_Kh[M_ * H_];
__device__ __nv_bfloat16 g_Kl[M_ * H_];
__device__ __nv_bfloat16 g_Vh[M_ * H_];
__device__ __nv_bfloat16 g_Vl[M_ * H_];
__device__ __nv_bfloat16 g_Ch[M_ * H_];
__device__ __nv_bfloat16 g_Cl[M_ * H_];
__device__ __nv_bfloat16 g_hsh[M_ * H_];
__device__ __nv_bfloat16 g_hsl[M_ * H_];
__device__ __nv_bfloat16 g_Wh[4 * H_ * H_];
__device__ __nv_bfloat16 g_Wl[4 * H_ * H_];

// ---------------------------------------------------------------------------
// fp32 -> (bf16 hi, bf16 lo) split, vectorized
// ---------------------------------------------------------------------------
__global__ __launch_bounds__(256)
void split_kernel(const float* __restrict__ x, __nv_bfloat16* __restrict__ hi,
                  __nv_bfloat16* __restrict__ lo, int n)
{
    int i = (blockIdx.x * 256 + threadIdx.x) * 4;
    if (i >= n) return;
    float4 v = *(const float4*)(x + i);
    __nv_bfloat16 h0 = __float2bfloat16(v.x);
    __nv_bfloat16 h1 = __float2bfloat16(v.y);
    __nv_bfloat16 h2 = __float2bfloat16(v.z);
    __nv_bfloat16 h3 = __float2bfloat16(v.w);
    __nv_bfloat16 l0 = __float2bfloat16(v.x - __bfloat162float(h0));
    __nv_bfloat16 l1 = __float2bfloat16(v.y - __bfloat162float(h1));
    __nv_bfloat16 l2 = __float2bfloat16(v.z - __bfloat162float(h2));
    __nv_bfloat16 l3 = __float2bfloat16(v.w - __bfloat162float(h3));
    __nv_bfloat162* hp = (__nv_bfloat162*)(hi + i);
    __nv_bfloat162* lp = (__nv_bfloat162*)(lo + i);
    hp[0] = __nv_bfloat162(h0, h1);
    hp[1] = __nv_bfloat162(h2, h3);
    lp[0] = __nv_bfloat162(l0, l1);
    lp[1] = __nv_bfloat162(l2, l3);
}

// ---------------------------------------------------------------------------
// mma.sync GEMM: acc[m][n] = sum_k A[m][k]*W[n][k] + bias[n]
// Output either fp32 (+resid) or bf16 hi/lo split.
// CTA 128x128, BK=32, 8 warps (2x4), warp tile 64x32, double-buffered cp.async.
// ---------------------------------------------------------------------------
#define SPAD_G 40
#define GK_ITERS 96        // 3 segments * (1024/32)

__global__ __launch_bounds__(256)
void gemm_mma(const __nv_bfloat16* __restrict__ Ah, const __nv_bfloat16* __restrict__ Al,
              const __nv_bfloat16* __restrict__ Wh, const __nv_bfloat16* __restrict__ Wl,
              const float* __restrict__ bias, const float* __restrict__ resid,
              float* __restrict__ Cf,
              __nv_bfloat16* __restrict__ Oh, __nv_bfloat16* __restrict__ Ol)
{
    __shared__ __nv_bfloat16 As[2][128][SPAD_G];
    __shared__ __nv_bfloat16 Bs[2][128][SPAD_G];

    const int tid = threadIdx.x;
    const int wid = tid >> 5;
    const int lane = tid & 31;
    const int wm = wid & 1;
    const int wn = wid >> 1;
    const int row0 = blockIdx.y * 128;
    const int col0 = blockIdx.x * 128;

    const __nv_bfloat16* aSeg[3] = {Ah, Ah, Al};
    const __nv_bfloat16* wSeg[3] = {Wh, Wl, Wh};

    const int l_row = tid >> 1;
    const int l_c8a = (tid & 1) * 2;

    auto load_stage = [&](int it, int st) {
        const int seg = it >> 5;
        const int k0 = (it & 31) * 32;
        const __nv_bfloat16* Ag = aSeg[seg];
        const __nv_bfloat16* Wg = wSeg[seg];
        uint32_t sa = smem_to_u32(&As[st][l_row][0]);
        uint32_t sb = smem_to_u32(&Bs[st][l_row][0]);
        const __nv_bfloat16* ga = Ag + (size_t)(row0 + l_row) * H_ + k0;
        const __nv_bfloat16* gb = Wg + (size_t)(col0 + l_row) * H_ + k0;
        #pragma unroll
        for (int c = 0; c < 2; c++) {
            int c8 = l_c8a + c;
            CP_ASYNC16(sa + c8 * 16, ga + c8 * 8);
            CP_ASYNC16(sb + c8 * 16, gb + c8 * 8);
        }
    };

    float acc[4][4][4];
    #pragma unroll
    for (int i = 0; i < 4; i++)
        #pragma unroll
        for (int j = 0; j < 4; j++)
            #pragma unroll
            for (int e = 0; e < 4; e++) acc[i][j][e] = 0.f;

    load_stage(0, 0);
    CP_COMMIT();

    for (int it = 0; it < GK_ITERS; it++) {
        CP_WAIT0();
        __syncthreads();
        if (it + 1 < GK_ITERS) load_stage(it + 1, (it + 1) & 1);
        CP_COMMIT();

        const int st = it & 1;
        const int t16 = lane & 15;
        uint32_t aBase = smem_to_u32(&As[st][wm * 64 + t16][0]);
        uint32_t bBase = smem_to_u32(&Bs[st][wn * 32 + (t16 & 7)][0]);
        const int aKoff = (lane >> 4) * 8;
        const int bKoff = (t16 >> 3) * 8;

        #pragma unroll
        for (int ks = 0; ks < 2; ks++) {
            const int k = ks * 16;
            uint32_t a[4][4];
            #pragma unroll
            for (int mf = 0; mf < 4; mf++)
                ldsm_x4(a[mf][0], a[mf][1], a[mf][2], a[mf][3],
                        aBase + (mf * 16 * SPAD_G + k + aKoff) * 2);
            uint32_t b[4][2];
            #pragma unroll
            for (int nf = 0; nf < 4; nf++)
                ldsm_x2(b[nf][0], b[nf][1],
                        bBase + (nf * 8 * SPAD_G + k + bKoff) * 2);
            #pragma unroll
            for (int mf = 0; mf < 4; mf++)
                #pragma unroll
                for (int nf = 0; nf < 4; nf++)
                    mma_16816(acc[mf][nf], a[mf][0], a[mf][1], a[mf][2], a[mf][3],
                              b[nf][0], b[nf][1]);
        }
        __syncthreads();
    }

    // Epilogue
    const int mBase = row0 + wm * 64 + (lane >> 2);
    const int nBase = col0 + wn * 32 + (lane & 3) * 2;
    #pragma unroll
    for (int mf = 0; mf < 4; mf++) {
        #pragma unroll
        for (int nf = 0; nf < 4; nf++) {
            const int m0 = mBase + mf * 16;
            const int n0 = nBase + nf * 8;
            float bx = bias[n0], by = bias[n0 + 1];
            float v00 = acc[mf][nf][0] + bx, v01 = acc[mf][nf][1] + by;
            float v10 = acc[mf][nf][2] + bx, v11 = acc[mf][nf][3] + by;
            if (Oh) {
                // bf16 hi/lo split output
                __nv_bfloat16 h00 = __float2bfloat16(v00), h01 = __float2bfloat16(v01);
                __nv_bfloat16 h10 = __float2bfloat16(v10), h11 = __float2bfloat16(v11);
                *(uint32_t*)&Oh[(size_t)m0 * H_ + n0] =
                    pack_bf2(__bfloat162float(h00), __bfloat162float(h01));
                *(uint32_t*)&Oh[(size_t)(m0 + 8) * H_ + n0] =
                    pack_bf2(__bfloat162float(h10), __bfloat162float(h11));
                *(uint32_t*)&Ol[(size_t)m0 * H_ + n0] =
                    pack_bf2(v00 - __bfloat162float(h00), v01 - __bfloat162float(h01));
                *(uint32_t*)&Ol[(size_t)(m0 + 8) * H_ + n0] =
                    pack_bf2(v10 - __bfloat162float(h10), v11 - __bfloat162float(h11));
            } else {
                if (resid) {
                    float2 r0 = *(const float2*)&resid[(size_t)m0 * H_ + n0];
                    float2 r1 = *(const float2*)&resid[(size_t)(m0 + 8) * H_ + n0];
                    v00 += r0.x; v01 += r0.y;
                    v10 += r1.x; v11 += r1.y;
                }
                *(float2*)&Cf[(size_t)m0 * H_ + n0] = make_float2(v00, v01);
                *(float2*)&Cf[(size_t)(m0 + 8) * H_ + n0] = make_float2(v10, v11);
            }
        }
    }
}

// ---------------------------------------------------------------------------
// Flash attention via mma.sync, split-bf16 (3-term QK, 3-term PV).
// CTA: 128 q rows (8 warps x 16), KV tile 32, double-buffered smem.
// ---------------------------------------------------------------------------
#define FBKV 32
#define FSPAD 72
#define FNT (S_ / FBKV)    // 64 tiles

__global__ __launch_bounds__(256)
void flash_mma(const __nv_bfloat16* __restrict__ Qh, const __nv_bfloat16* __restrict__ Ql,
               const __nv_bfloat16* __restrict__ Kh, const __nv_bfloat16* __restrict__ Kl,
               const __nv_bfloat16* __restrict__ Vh, const __nv_bfloat16* __restrict__ Vl,
               __nv_bfloat16* __restrict__ Ch, __nv_bfloat16* __restrict__ Cl)
{
    // [stage][mat: 0=Kh 1=Kl 2=Vh 3=Vl][row][col]
    __shared__ __nv_bfloat16 sKV[2][4][FBKV][FSPAD];

    const int tid = threadIdx.x;
    const int wid = tid >> 5;
    const int lane = tid & 31;
    const int b = blockIdx.z;
    const int h = blockIdx.y;
    const int q0 = blockIdx.x * 128;

    const int r = lane >> 2;
    const int c2 = (lane & 3) * 2;
    const size_t qrow0 = (size_t)(b * S_ + q0 + wid * 16);
    const int hcol = h * HD_;

    // ---- Q fragments (hi/lo), pre-scaled by 1/8 (exact in bf16) ----
    uint32_t qh[4][4], ql[4][4];
    {
        const __nv_bfloat162 sc8 = __floats2bfloat162_rn(0.125f, 0.125f);
        #pragma unroll
        for (int kf = 0; kf < 4; kf++) {
            const int c = kf * 16 + c2;
            const size_t i00 = (qrow0 + r) * H_ + hcol + c;
            const size_t i10 = (qrow0 + r + 8) * H_ + hcol + c;
            __nv_bfloat162 t;
            t = __hmul2(*(const __nv_bfloat162*)&Qh[i00], sc8);     qh[kf][0] = *(uint32_t*)&t;
            t = __hmul2(*(const __nv_bfloat162*)&Qh[i10], sc8);     qh[kf][1] = *(uint32_t*)&t;
            t = __hmul2(*(const __nv_bfloat162*)&Qh[i00 + 8], sc8); qh[kf][2] = *(uint32_t*)&t;
            t = __hmul2(*(const __nv_bfloat162*)&Qh[i10 + 8], sc8); qh[kf][3] = *(uint32_t*)&t;
            t = __hmul2(*(const __nv_bfloat162*)&Ql[i00], sc8);     ql[kf][0] = *(uint32_t*)&t;
            t = __hmul2(*(const __nv_bfloat162*)&Ql[i10], sc8);     ql[kf][1] = *(uint32_t*)&t;
            t = __hmul2(*(const __nv_bfloat162*)&Ql[i00 + 8], sc8); ql[kf][2] = *(uint32_t*)&t;
            t = __hmul2(*(const __nv_bfloat162*)&Ql[i10 + 8], sc8); ql[kf][3] = *(uint32_t*)&t;
        }
    }

    float o[8][4];
    #pragma unroll
    for (int d = 0; d < 8; d++)
        #pragma unroll
        for (int e = 0; e < 4; e++) o[d][e] = 0.f;
    float mrow0 = -1e30f, mrow1 = -1e30f;
    float lrow0 = 0.f, lrow1 = 0.f;

    // loader: 4 mats x 32 rows x 8 chunks(16B) = 1024 chunks; 4 per thread
    const __nv_bfloat16* matp[4] = {Kh, Kl, Vh, Vl};
    const int l_mat = tid >> 6;
    const int l_row = (tid & 63) >> 1;
    const int l_c0 = (tid & 1) * 4;

    auto load_stage = [&](int tile, int st) {
        const __nv_bfloat16* g = matp[l_mat] +
            (size_t)(b * S_ + tile * FBKV + l_row) * H_ + hcol;
        uint32_t sb = smem_to_u32(&sKV[st][l_mat][l_row][0]);
        #pragma unroll
        for (int c = 0; c < 4; c++) {
            int ch = l_c0 + c;
            CP_ASYNC16(sb + ch * 16, g + ch * 8);
        }
    };

    load_stage(0, 0);
    CP_COMMIT();

    const int t16 = lane & 15;

    for (int it = 0; it < FNT; it++) {
        CP_WAIT0();
        __syncthreads();
        if (it + 1 < FNT) load_stage(it + 1, (it + 1) & 1);
        CP_COMMIT();

        const int st = it & 1;

        // ---- QK^T: scores [16 x 32], 4 n-frags ----
        float sc[4][4];
        #pragma unroll
        for (int nf = 0; nf < 4; nf++) {
            sc[nf][0] = sc[nf][1] = sc[nf][2] = sc[nf][3] = 0.f;
            uint32_t kAddrH = smem_to_u32(&sKV[st][0][nf * 8 + (t16 & 7)][(t16 >> 3) * 8]);
            uint32_t kAddrL = smem_to_u32(&sKV[st][1][nf * 8 + (t16 & 7)][(t16 >> 3) * 8]);
            #pragma unroll
            for (int kf = 0; kf < 4; kf++) {
                uint32_t bh0, bh1, bl0, bl1;
                ldsm_x2(bh0, bh1, kAddrH + kf * 32);   // 16 bf16 = 32B per kstep
                ldsm_x2(bl0, bl1, kAddrL + kf * 32);
                mma_16816(sc[nf], qh[kf][0], qh[kf][1], qh[kf][2], qh[kf][3], bh0, bh1);
                mma_16816(sc[nf], ql[kf][0], ql[kf][1], ql[kf][2], ql[kf][3], bh0, bh1);
                mma_16816(sc[nf], qh[kf][0], qh[kf][1], qh[kf][2], qh[kf][3], bl0, bl1);
            }
        }

        // ---- online softmax ----
        float mx0 = sc[0][0], mx1 = sc[0][2];
        #pragma unroll
        for (int nf = 0; nf < 4; nf++) {
            mx0 = fmaxf(mx0, fmaxf(sc[nf][0], sc[nf][1]));
            mx1 = fmaxf(mx1, fmaxf(sc[nf][2], sc[nf][3]));
        }
        mx0 = fmaxf(mx0, __shfl_xor_sync(0xffffffffu, mx0, 1));
        mx0 = fmaxf(mx0, __shfl_xor_sync(0xffffffffu, mx0, 2));
        mx1 = fmaxf(mx1, __shfl_xor_sync(0xffffffffu, mx1, 1));
        mx1 = fmaxf(mx1, __shfl_xor_sync(0xffffffffu, mx1, 2));
        const float mn0 = fmaxf(mrow0, mx0);
        const float mn1 = fmaxf(mrow1, mx1);
        const float cor0 = __expf(mrow0 - mn0);
        const float cor1 = __expf(mrow1 - mn1);
        mrow0 = mn0; mrow1 = mn1;
        lrow0 *= cor0; lrow1 *= cor1;
        #pragma unroll
        for (int d = 0; d < 8; d++) {
            o[d][0] *= cor0; o[d][1] *= cor0;
            o[d][2] *= cor1; o[d][3] *= cor1;
        }
        float ls0 = 0.f, ls1 = 0.f;
        #pragma unroll
        for (int nf = 0; nf < 4; nf++) {
            sc[nf][0] = __expf(sc[nf][0] - mn0);
            sc[nf][1] = __expf(sc[nf][1] - mn0);
            sc[nf][2] = __expf(sc[nf][2] - mn1);
            sc[nf][3] = __expf(sc[nf][3] - mn1);
            ls0 += sc[nf][0] + sc[nf][1];
            ls1 += sc[nf][2] + sc[nf][3];
        }
        lrow0 += ls0; lrow1 += ls1;

        // ---- P*V: o[16 x 64] += P[16 x 32] * V[32 x 64] ----
        #pragma unroll
        for (int kc = 0; kc < 2; kc++) {
            // A frags from score frags 2kc, 2kc+1 (hi/lo split)
            uint32_t ah[4], al[4];
            {
                const float* s0 = sc[2 * kc];
                const float* s1 = sc[2 * kc + 1];
                __nv_bfloat16 h;
                float p, q2;
                float h0f, h1f;
                p = s0[0]; h = __float2bfloat16(p); h0f = __bfloat162float(h);
                q2 = s0[1]; __nv_bfloat16 hb = __float2bfloat16(q2); h1f = __bfloat162float(hb);
                ah[0] = pack_bf2(h0f, h1f); al[0] = pack_bf2(p - h0f, q2 - h1f);
                p = s0[2]; h = __float2bfloat16(p); h0f = __bfloat162float(h);
                q2 = s0[3]; hb = __float2bfloat16(q2); h1f = __bfloat162float(hb);
                ah[1] = pack_bf2(h0f, h1f); al[1] = pack_bf2(p - h0f, q2 - h1f);
                p = s1[0]; h = __float2bfloat16(p); h0f = __bfloat162float(h);
                q2 = s1[1]; hb = __float2bfloat16(q2); h1f = __bfloat162float(hb);
                ah[2] = pack_bf2(h0f, h1f); al[2] = pack_bf2(p - h0f, q2 - h1f);
                p = s1[2]; h = __float2bfloat16(p); h0f = __bfloat162float(h);
                q2 = s1[3]; hb = __float2bfloat16(q2); h1f = __bfloat162float(hb);
                ah[3] = pack_bf2(h0f, h1f); al[3] = pack_bf2(p - h0f, q2 - h1f);
            }
            // V frag addresses: trans ldmatrix
            const int vt = lane >> 3;          // tile 0..3
            const int vr = lane & 7;
            const int vrow = kc * 16 + (vt & 1) * 8 + vr;
            const int vcol8 = (vt >> 1) * 8;
            #pragma unroll
            for (int d16 = 0; d16 < 4; d16++) {
                uint32_t bh0, bh1, bh2, bh3;
                ldsm_x4t(bh0, bh1, bh2, bh3,
                         smem_to_u32(&sKV[st][2][vrow][d16 * 16 + vcol8]));
                mma_16816(o[2 * d16 + 0], ah[0], ah[1], ah[2], ah[3], bh0, bh1);
                mma_16816(o[2 * d16 + 1], ah[0], ah[1], ah[2], ah[3], bh2, bh3);
                mma_16816(o[2 * d16 + 0], al[0], al[1], al[2], al[3], bh0, bh1);
                mma_16816(o[2 * d16 + 1], al[0], al[1], al[2], al[3], bh2, bh3);
                uint32_t bl0, bl1, bl2, bl3;
                ldsm_x4t(bl0, bl1, bl2, bl3,
                         smem_to_u32(&sKV[st][3][vrow][d16 * 16 + vcol8]));
                mma_16816(o[2 * d16 + 0], ah[0], ah[1], ah[2], ah[3], bl0, bl1);
                mma_16816(o[2 * d16 + 1], ah[0], ah[1], ah[2], ah[3], bl2, bl3);
            }
        }
        __syncthreads();
    }

    // ---- epilogue ----
    lrow0 += __shfl_xor_sync(0xffffffffu, lrow0, 1);
    lrow0 += __shfl_xor_sync(0xffffffffu, lrow0, 2);
    lrow1 += __shfl_xor_sync(0xffffffffu, lrow1, 1);
    lrow1 += __shfl_xor_sync(0xffffffffu, lrow1, 2);
    const float inv0 = 1.f / lrow0;
    const float inv1 = 1.f / lrow1;

    const size_t row0i = (qrow0 + r) * H_ + hcol;
    const size_t row1i = (qrow0 + r + 8) * H_ + hcol;
    #pragma unroll
    for (int d = 0; d < 8; d++) {
        const int col = d * 8 + c2;
        float v00 = o[d][0] * inv0, v01 = o[d][1] * inv0;
        float v10 = o[d][2] * inv1, v11 = o[d][3] * inv1;
        __nv_bfloat16 h00 = __float2bfloat16(v00), h01 = __float2bfloat16(v01);
        __nv_bfloat16 h10 = __float2bfloat16(v10), h11 = __float2bfloat16(v11);
        *(uint32_t*)&Ch[row0i + col] = pack_bf2(__bfloat162float(h00), __bfloat162float(h01));
        *(uint32_t*)&Ch[row1i + col] = pack_bf2(__bfloat162float(h10), __bfloat162float(h11));
        *(uint32_t*)&Cl[row0i + col] =
            pack_bf2(v00 - __bfloat162float(h00), v01 - __bfloat162float(h01));
        *(uint32_t*)&Cl[row1i + col] =
            pack_bf2(v10 - __bfloat162float(h10), v11 - __bfloat162float(h11));
    }
}

// ---------------------------------------------------------------------------
// LayerNorm
// ---------------------------------------------------------------------------
__global__ __launch_bounds__(256)
void layernorm(const float* __restrict__ X, const float* __restrict__ gamma,
               const float* __restrict__ beta, float* __restrict__ Out)
{
    __shared__ float red[8];
    __shared__ float bc;

    const int row = blockIdx.x;
    const int tid = threadIdx.x;
    const float* x = X + (size_t)row * H_;

    float v[4];
    float s = 0.f;
    #pragma unroll
    for (int i = 0; i < 4; i++) { v[i] = x[tid + 256 * i]; s += v[i]; }

    #pragma unroll
    for (int o = 16; o > 0; o >>= 1) s += __shfl_xor_sync(0xffffffffu, s, o);
    if ((tid & 31) == 0) red[tid >> 5] = s;
    __syncthreads();
    if (tid == 0) {
        float t = 0.f;
        #pragma unroll
        for (int i = 0; i < 8; i++) t += red[i];
        bc = t * (1.f / H_);
    }
    __syncthreads();
    const float mu = bc;

    float vs = 0.f;
    #pragma unroll
    for (int i = 0; i < 4; i++) { float d = v[i] - mu; vs += d * d; }
    #pragma unroll
    for (int o = 16; o > 0; o >>= 1) vs += __shfl_xor_sync(0xffffffffu, vs, o);
    __syncthreads();
    if ((tid & 31) == 0) red[tid >> 5] = vs;
    __syncthreads();
    if (tid == 0) {
        float t = 0.f;
        #pragma unroll
        for (int i = 0; i < 8; i++) t += red[i];
        bc = t * (1.f / H_);
    }
    __syncthreads();
    const float rstd = rsqrtf(bc + LN_EPS);

    #pragma unroll
    for (int i = 0; i < 4; i++) {
        int col = tid + 256 * i;
        Out[(size_t)row * H_ + col] = (v[i] - mu) * rstd * gamma[col] + beta[col];
    }
}

// ---------------------------------------------------------------------------
// Launch
// ---------------------------------------------------------------------------
extern "C" void kernel_launch(void* const* d_in, const int* in_sizes, int n_in,
                              void* d_out, int out_size)
{
    const float* hs    = (const float*)d_in[0];
    const float* Wq    = (const float*)d_in[1];
    const float* bq    = (const float*)d_in[2];
    const float* Wk    = (const float*)d_in[3];
    const float* bk    = (const float*)d_in[4];
    const float* Wv    = (const float*)d_in[5];
    const float* bv    = (const float*)d_in[6];
    const float* Wd    = (const float*)d_in[7];
    const float* bd    = (const float*)d_in[8];
    const float* gamma = (const float*)d_in[9];
    const float* beta  = (const float*)d_in[10];
    float* out = (float*)d_out;

    float* Xp;
    __nv_bfloat16 *Qh, *Ql, *Kh, *Kl, *Vh, *Vl, *Ch, *Cl, *hsh, *hsl, *Whp, *Wlp;
    cudaGetSymbolAddress((void**)&Xp, g_X);
    cudaGetSymbolAddress((void**)&Qh, g_Qh);
    cudaGetSymbolAddress((void**)&Ql, g_Ql);
    cudaGetSymbolAddress((void**)&Kh, g_Kh);
    cudaGetSymbolAddress((void**)&Kl, g_Kl);
    cudaGetSymbolAddress((void**)&Vh, g_Vh);
    cudaGetSymbolAddress((void**)&Vl, g_Vl);
    cudaGetSymbolAddress((void**)&Ch, g_Ch);
    cudaGetSymbolAddress((void**)&Cl, g_Cl);
    cudaGetSymbolAddress((void**)&hsh, g_hsh);
    cudaGetSymbolAddress((void**)&hsl, g_hsl);
    cudaGetSymbolAddress((void**)&Whp, g_Wh);
    cudaGetSymbolAddress((void**)&Wlp, g_Wl);

    const int nAct = M_ * H_;
    const int nW   = H_ * H_;

    split_kernel<<<nAct / (256 * 4), 256>>>(hs, hsh, hsl, nAct);
    split_kernel<<<nW / (256 * 4), 256>>>(Wq, Whp + 0 * nW, Wlp + 0 * nW, nW);
    split_kernel<<<nW / (256 * 4), 256>>>(Wk, Whp + 1 * nW, Wlp + 1 * nW, nW);
    split_kernel<<<nW / (256 * 4), 256>>>(Wv, Whp + 2 * nW, Wlp + 2 * nW, nW);
    split_kernel<<<nW / (256 * 4), 256>>>(Wd, Whp + 3 * nW, Wlp + 3 * nW, nW);

    dim3 gg(H_ / 128, M_ / 128);   // (8, 32)
    gemm_mma<<<gg, 256>>>(hsh, hsl, Whp + 0 * nW, Wlp + 0 * nW, bq, nullptr, nullptr, Qh, Ql);
    gemm_mma<<<gg, 256>>>(hsh, hsl, Whp + 1 * nW, Wlp + 1 * nW, bk, nullptr, nullptr, Kh, Kl);
    gemm_mma<<<gg, 256>>>(hsh, hsl, Whp + 2 * nW, Wlp + 2 * nW, bv, nullptr, nullptr, Vh, Vl);

    flash_mma<<<dim3(S_ / 128, NH_, B_), 256>>>(Qh, Ql, Kh, Kl, Vh, Vl, Ch, Cl);

    gemm_mma<<<gg, 256>>>(Ch, Cl, Whp + 3 * nW, Wlp + 3 * nW, bd, hs, Xp, nullptr, nullptr);

    layernorm<<<M_, 256>>>(Xp, gamma, beta, out);
}